// round 11
// baseline (speedup 1.0000x reference)
#include <cuda_runtime.h>
#include <cuda_fp16.h>

// ---------------------------------------------------------------------------
// Fused MoE via grouped fp16 mma.sync (m16n8k16) GEMMs, fp32 accumulate.
//   T=1024, H=2048, F=1408, E=32, K=6.
// zero_out -> prep -> x->fp16 -> GEMM1 (gate+up, fused SwiGLU -> Hb fp16)
//          -> GEMM2 (fused weighted atomic scatter -> out)
// Staging via cp.async.bulk (one op per row-chunk) + mbarrier ring: removes
// the measured LDGSTS-issue bottleneck (0.84 ops/cyc/SM ~ LSU floor).
// ---------------------------------------------------------------------------

#define T_TOK 1024
#define HID   2048
#define FF    1408
#define NEXP  32
#define TOPK  6
#define NA    (T_TOK * TOPK)    // 6144
#define GUN   (2 * FF)          // 2816

typedef unsigned int u32;

// smem: 4 stages: A 256 rows x 80B (fp16) = 20KB; B 128 rows x 160B (fp32)
// = 20KB.  A at [0,81920), B at [81920,163840), mbarriers at [163840,163904).
#define AST   20480u
#define BBASE 81920u
#define BST   20480u
#define MBOFF 163840u
#define SMB   163904
#define XSTR  68                // swiglu exchange stride (floats)

// ---------------- device scratch -------------------------------------------
__device__ int    d_count[NEXP];
__device__ int    d_off[NEXP];
__device__ int    d_tok[NA];
__device__ float  d_wts[NA];
__device__ __half d_xh[(size_t)T_TOK * HID];   // x in fp16
__device__ __half d_Hh[(size_t)NA * FF];       // swiglu output in fp16

// ---------------- PTX helpers ----------------------------------------------
__device__ __forceinline__ u32 smem_u32(const void* p) {
    u32 a;
    asm("{ .reg .u64 t; cvta.to.shared.u64 t, %1; cvt.u32.u64 %0, t; }"
        : "=r"(a) : "l"(p));
    return a;
}
__device__ __forceinline__ u32 pack2h(float2 v) {   // {lo=v.x, hi=v.y} fp16x2
    u32 r;
    asm("cvt.rn.f16x2.f32 %0, %1, %2;" : "=r"(r) : "f"(v.y), "f"(v.x));
    return r;
}
#define MBAR_INIT(a, c) \
    asm volatile("mbarrier.init.shared.b64 [%0], %1;" :: "r"(a), "r"(c) : "memory")
#define MBAR_ARRTX(a, tx) \
    asm volatile("mbarrier.arrive.expect_tx.shared.b64 _, [%0], %1;" \
                 :: "r"(a), "r"(tx) : "memory")
#define BULK(dst, src, sz, mb) \
    asm volatile("cp.async.bulk.shared::cluster.global.mbarrier::complete_tx::bytes " \
                 "[%0], [%1], %2, [%3];" \
                 :: "r"(dst), "l"(src), "r"(sz), "r"(mb) : "memory")
#define MBAR_WAIT(a, ph) do {                                                  \
    u32 _m = (a), _p = (ph), _d;                                               \
    asm volatile("{\n\t.reg .pred p;\n\t"                                      \
        "mbarrier.try_wait.parity.acquire.cta.shared::cta.b64 p, [%1], %2;\n\t"\
        "selp.b32 %0, 1, 0, p;\n\t}" : "=r"(_d) : "r"(_m), "r"(_p) : "memory");\
    if (!_d) {                                                                 \
        asm volatile("{\n\t.reg .pred P1;\n\tWL_%=:\n\t"                       \
            "mbarrier.try_wait.parity.acquire.cta.shared::cta.b64 P1, [%0], %1, 0x989680;\n\t" \
            "@P1 bra.uni WD_%=;\n\tbra.uni WL_%=;\n\tWD_%=:\n\t}"              \
            :: "r"(_m), "r"(_p) : "memory");                                   \
    } } while (0)

__device__ __forceinline__ void mma16(float* d, u32 a0, u32 a1, u32 a2, u32 a3,
                                      u32 b0, u32 b1) {
    asm volatile(
        "mma.sync.aligned.m16n8k16.row.col.f32.f16.f16.f32 "
        "{%0,%1,%2,%3}, {%4,%5,%6,%7}, {%8,%9}, {%0,%1,%2,%3};"
        : "+f"(d[0]), "+f"(d[1]), "+f"(d[2]), "+f"(d[3])
        : "r"(a0), "r"(a1), "r"(a2), "r"(a3), "r"(b0), "r"(b1));
}

// ---------------- prep / convert -------------------------------------------
__global__ void k_zero_out(float4* out) {
    out[blockIdx.x * blockDim.x + threadIdx.x] = make_float4(0.f, 0.f, 0.f, 0.f);
}
__global__ void k_x2h(const float2* __restrict__ x) {
    int i = blockIdx.x * blockDim.x + threadIdx.x;   // 1M threads, 2 el each
    float2 v = x[i];
    ((__half2*)d_xh)[i] = __floats2half2_rn(v.x, v.y);
}
__global__ __launch_bounds__(256) void k_prep(const int* __restrict__ ids32,
                                              const float* __restrict__ tw) {
    __shared__ int f;
    __shared__ int scnt[NEXP];
    __shared__ int sfill[NEXP];
    const int tid = threadIdx.x;
    if (tid < NEXP) scnt[tid] = 0;
    if (tid == 0) f = 0;
    __syncthreads();
    int local = 0;
    for (int i = tid; i < NA / 2; i += 256)
        if (ids32[2 * i + 1] != 0) local = 1;
    if (local) f = 1;
    __syncthreads();
    const int flag = f;   // 1 => int32 ids
    for (int i = tid; i < NA; i += 256) {
        int e = flag ? ids32[i] : ids32[2 * i];
        atomicAdd(&scnt[e], 1);
    }
    __syncthreads();
    if (tid == 0) {
        int off = 0;
        for (int e = 0; e < NEXP; e++) {
            d_off[e] = off; sfill[e] = off;
            d_count[e] = scnt[e];
            off += scnt[e];
        }
    }
    __syncthreads();
    for (int i = tid; i < NA; i += 256) {
        int e = flag ? ids32[i] : ids32[2 * i];
        int pos = atomicAdd(&sfill[e], 1);
        d_tok[pos] = i / TOPK;
        d_wts[pos] = tw[i];
    }
}

// ---------------- grouped fp16 GEMM ----------------------------------------
// BM=256, BK=32, 512 threads (16 warps). Warp tile 64x32: four 16-row stripes
// at rows (wid&3)*16 + mt*64 (SMSP-interleaved), 32 cols at warpN=(wid>>2)*32.
// Staging: warps 0..7 bulk-copy A rows (1 row/lane, 64B), warps 8..11 B rows
// (1 row/lane, 128B); per-warp elected mbarrier.arrive.expect_tx; 4-stage ring.
// MODE 0: B tile = 64 gate rows + 64 up rows of same h-cols (n0=bx*64);
//   groups 0,1 gate / 2,3 up; up accs -> smem; gate applies silu*u -> d_Hh.
// MODE 1: BN=128 (n0=bx*128), weighted atomic scatter into Out.
template<int KDIM, int MODE>
__global__ __launch_bounds__(512, 1) void k_gemm(const float* __restrict__ Bw,
                                                 float* __restrict__ Out) {
    constexpr int NIT = KDIM / 32;
    extern __shared__ char smem[];
    const int e = blockIdx.y;
    const int cnt = d_count[e];
    if (cnt == 0) return;
    const int row0e = d_off[e];
    const int n0 = blockIdx.x * (MODE == 0 ? 64 : 128);
    const long long bStride = (MODE == 0) ? (long long)GUN * HID
                                          : (long long)HID * FF;
    const __half* A = (MODE == 0) ? d_xh : d_Hh;

    const int tid = threadIdx.x;
    const int wid = tid >> 5, lane = tid & 31;
    const int r4 = lane >> 2, c4 = lane & 3;
    const int s16   = (wid & 3) * 16;       // SMSP-interleaved M base
    const int group = wid >> 2;             // 0..3 N-group
    const int warpN = group * 32;
    const u32 sb = smem_u32(smem);
    const u32 mb = sb + MBOFF;

    if (tid == 0) {
#pragma unroll
        for (int s = 0; s < 4; s++) MBAR_INIT(mb + s * 8, 12);
    }
    __syncthreads();

    // producer geometry: warps 0..7 -> A row wid*32+lane; 8..11 -> B row
    const int prow = (wid < 8) ? (wid * 32 + lane) : ((wid - 8) * 32 + lane);
    const float* bSrcF = nullptr;
    u32 bDst = 0;
    if (wid >= 8 && wid < 12) {
        long long gr = (MODE == 0)
            ? ((prow < 64) ? (long long)(n0 + prow)
                           : (long long)(FF + n0 + prow - 64))
            : (long long)(n0 + prow);
        bSrcF = Bw + (long long)e * bStride + gr * KDIM;
        bDst  = sb + BBASE + (u32)prow * 160u;
    }
    const u32 aDst = sb + (u32)prow * 80u;

    int gg = 0;                              // global pipeline iteration
    for (int m0 = 0; m0 < cnt; m0 += 256) {
        // per-tile A producer state
        const __half* aSrc = nullptr;
        int aval = 0; u32 abytes = 0;
        if (wid < 8) {
            aval = (m0 + prow) < cnt;
            long long srow = 0;
            if (aval)
                srow = (MODE == 0) ? (long long)d_tok[row0e + m0 + prow]
                                   : (long long)(row0e + m0 + prow);
            aSrc = A + srow * KDIM;
            abytes = (u32)__popc(__ballot_sync(0xffffffffu, aval)) * 64u;
        }
        const int rem = cnt - m0;
        const int tv = rem - s16;
        const int mtMax = (tv <= 0) ? 0 : ((tv + 63) >> 6 > 4 ? 4 : (tv + 63) >> 6);

        float acc[4][4][4];
#pragma unroll
        for (int mt = 0; mt < 4; mt++)
#pragma unroll
            for (int nt = 0; nt < 4; nt++)
#pragma unroll
                for (int q = 0; q < 4; q++) acc[mt][nt][q] = 0.f;

#define ISSUE(g, k0) do {                                                  \
        u32 _s = (u32)(g) & 3u;                                            \
        if (wid < 8) {                                                     \
            if (lane == 0) MBAR_ARRTX(mb + _s * 8, abytes);                \
            if (aval) BULK(aDst + _s * AST, aSrc + (k0), 64u, mb + _s * 8);\
        } else if (wid < 12) {                                             \
            if (lane == 0) MBAR_ARRTX(mb + _s * 8, 4096u);                 \
            BULK(bDst + _s * BST, bSrcF + (k0), 128u, mb + _s * 8);        \
        }                                                                  \
    } while (0)

        ISSUE(gg + 0, 0);
        ISSUE(gg + 1, 32);
        ISSUE(gg + 2, 64);

        for (int it = 0; it < NIT; it++) {
            const int g = gg + it;
            const int buf = g & 3;
            MBAR_WAIT(mb + buf * 8, (g >> 2) & 1);
            __syncthreads();
            if (it + 3 < NIT) ISSUE(gg + it + 3, (it + 3) * 32);

            const __half* Ah = (const __half*)(smem + buf * AST);
            const float*  Bf = (const float*)(smem + BBASE + buf * BST);
#pragma unroll
            for (int ks = 0; ks < 2; ks++) {
                u32 b[4][2];
#pragma unroll
                for (int nt = 0; nt < 4; nt++) {
                    int cb = (warpN + nt * 8 + r4) * 40 + ks * 16 + 2 * c4;
                    b[nt][0] = pack2h(*(const float2*)&Bf[cb]);
                    b[nt][1] = pack2h(*(const float2*)&Bf[cb + 8]);
                }
#pragma unroll
                for (int mt = 0; mt < 4; mt++) {
                    if (mt < mtMax) {
                        int ab = (s16 + mt * 64 + r4) * 40 + ks * 16 + 2 * c4;
                        u32 a0 = *(const u32*)&Ah[ab];          // fp16x2 direct
                        u32 a1 = *(const u32*)&Ah[ab + 320];    // +8 rows
                        u32 a2 = *(const u32*)&Ah[ab + 8];      // +8 k
                        u32 a3 = *(const u32*)&Ah[ab + 328];
#pragma unroll
                        for (int nt = 0; nt < 4; nt++)
                            mma16(acc[mt][nt], a0, a1, a2, a3,
                                  b[nt][0], b[nt][1]);
                    }
                }
            }
        }
        gg += NIT;

        if (MODE == 0) {
            // ---- fused SwiGLU epilogue: up groups -> smem, gate groups read
            float* xs = (float*)smem;
            __syncthreads();                    // pipeline smem now dead
            if (group >= 2) {
                const int xc = (group - 2) * 32;
#pragma unroll
                for (int mt = 0; mt < 4; mt++) {
                    int r = s16 + mt * 64 + r4;
#pragma unroll
                    for (int nt = 0; nt < 4; nt++) {
                        int col = xc + nt * 8 + c4 * 2;
                        *(float2*)&xs[r * XSTR + col] =
                            make_float2(acc[mt][nt][0], acc[mt][nt][1]);
                        *(float2*)&xs[(r + 8) * XSTR + col] =
                            make_float2(acc[mt][nt][2], acc[mt][nt][3]);
                    }
                }
            }
            __syncthreads();
            if (group < 2) {
                const int xc = group * 32;
#pragma unroll
                for (int mt = 0; mt < 4; mt++) {
                    int r = s16 + mt * 64 + r4;
                    int rloc = m0 + r;
#pragma unroll
                    for (int nt = 0; nt < 4; nt++) {
                        int col = xc + nt * 8 + c4 * 2;
                        if (rloc < cnt) {
                            float2 u = *(const float2*)&xs[r * XSTR + col];
                            float g0 = acc[mt][nt][0], g1 = acc[mt][nt][1];
                            float h0 = g0 / (1.f + __expf(-g0)) * u.x;
                            float h1 = g1 / (1.f + __expf(-g1)) * u.y;
                            *(__half2*)&d_Hh[(long long)(row0e + rloc) * FF
                                + n0 + col] = __floats2half2_rn(h0, h1);
                        }
                        if (rloc + 8 < cnt) {
                            float2 u = *(const float2*)&xs[(r + 8) * XSTR + col];
                            float g0 = acc[mt][nt][2], g1 = acc[mt][nt][3];
                            float h0 = g0 / (1.f + __expf(-g0)) * u.x;
                            float h1 = g1 / (1.f + __expf(-g1)) * u.y;
                            *(__half2*)&d_Hh[(long long)(row0e + rloc + 8) * FF
                                + n0 + col] = __floats2half2_rn(h0, h1);
                        }
                    }
                }
            }
        } else {
            // ---- weighted atomic scatter into Out ----
#pragma unroll
            for (int mt = 0; mt < 4; mt++) {
                int rloc = m0 + s16 + mt * 64 + r4;
                int v0 = rloc < cnt, v1 = (rloc + 8) < cnt;
                int t0 = 0, t1 = 0; float w0 = 0.f, w1 = 0.f;
                if (v0) { t0 = d_tok[row0e + rloc];     w0 = d_wts[row0e + rloc]; }
                if (v1) { t1 = d_tok[row0e + rloc + 8]; w1 = d_wts[row0e + rloc + 8]; }
#pragma unroll
                for (int nt = 0; nt < 4; nt++) {
                    int col = n0 + warpN + nt * 8 + c4 * 2;
                    if (v0) {
                        float* o = Out + (long long)t0 * HID + col;
                        atomicAdd(o,     w0 * acc[mt][nt][0]);
                        atomicAdd(o + 1, w0 * acc[mt][nt][1]);
                    }
                    if (v1) {
                        float* o = Out + (long long)t1 * HID + col;
                        atomicAdd(o,     w1 * acc[mt][nt][2]);
                        atomicAdd(o + 1, w1 * acc[mt][nt][3]);
                    }
                }
            }
        }
        __syncthreads();
#undef ISSUE
    }
}

// ---------------- launch ----------------------------------------------------
extern "C" void kernel_launch(void* const* d_in, const int* in_sizes, int n_in,
                              void* d_out, int out_size) {
    const float* x   = (const float*)d_in[0];
    const float* w1  = (const float*)d_in[1];
    const float* w2  = (const float*)d_in[2];
    const float* tw  = (const float*)d_in[3];
    const int*   ids = (const int*)d_in[4];
    float* out = (float*)d_out;

    cudaFuncSetAttribute(k_gemm<HID, 0>,
                         cudaFuncAttributeMaxDynamicSharedMemorySize, SMB);
    cudaFuncSetAttribute(k_gemm<FF, 1>,
                         cudaFuncAttributeMaxDynamicSharedMemorySize, SMB);

    k_zero_out<<<1024, 512>>>((float4*)out);
    k_x2h<<<2048, 512>>>((const float2*)x);
    k_prep<<<1, 256>>>(ids, tw);
    k_gemm<HID, 0><<<dim3(FF / 64, NEXP), 512, SMB>>>(w1, nullptr);
    k_gemm<FF, 1><<<dim3(HID / 128, NEXP), 512, SMB>>>(w2, out);
}

// round 12
// speedup vs baseline: 1.2167x; 1.2167x over previous
#include <cuda_runtime.h>
#include <cuda_fp16.h>

// ---------------------------------------------------------------------------
// Fused MoE via grouped fp16 mma.sync (m16n8k16) GEMMs, fp32 accumulate.
//   T=1024, H=2048, F=1408, E=32, K=6.
// zero_out -> prep -> x->fp16 -> GEMM1 (gate+up, fused SwiGLU -> Hb fp16)
//          -> GEMM2 (fused weighted atomic scatter -> out)
// cp.async (16B) staging - bulk-TMA path regressed (R11).  Wide BN tiles
// (128 h-cols / 256 cols) halve A re-staging: the LDGSTS-issue bottleneck.
// ---------------------------------------------------------------------------

#define T_TOK 1024
#define HID   2048
#define FF    1408
#define NEXP  32
#define TOPK  6
#define NA    (T_TOK * TOPK)    // 6144
#define GUN   (2 * FF)          // 2816

typedef unsigned int u32;

// smem: 4 stages: A 128 rows x 80B (fp16) = 10KB; B 256 rows x 160B (fp32)
// = 40KB.  A at [0,40960), B at [40960,204800).
#define AST   10240u
#define BBASE 40960u
#define BST   40960u
#define SMB   204800
#define XSTR  132               // swiglu exchange stride (floats)

// ---------------- device scratch -------------------------------------------
__device__ int    d_count[NEXP];
__device__ int    d_off[NEXP];
__device__ int    d_tok[NA];
__device__ float  d_wts[NA];
__device__ __half d_xh[(size_t)T_TOK * HID];   // x in fp16
__device__ __half d_Hh[(size_t)NA * FF];       // swiglu output in fp16

// ---------------- PTX helpers ----------------------------------------------
__device__ __forceinline__ u32 smem_u32(const void* p) {
    u32 a;
    asm("{ .reg .u64 t; cvta.to.shared.u64 t, %1; cvt.u32.u64 %0, t; }"
        : "=r"(a) : "l"(p));
    return a;
}
__device__ __forceinline__ u32 pack2h(float2 v) {   // {lo=v.x, hi=v.y} fp16x2
    u32 r;
    asm("cvt.rn.f16x2.f32 %0, %1, %2;" : "=r"(r) : "f"(v.y), "f"(v.x));
    return r;
}
#define CP16(dst, src, sz) \
    asm volatile("cp.async.cg.shared.global [%0], [%1], 16, %2;" \
                 :: "r"(dst), "l"(src), "r"(sz))
#define CP_COMMIT() asm volatile("cp.async.commit_group;" ::: "memory")
#define CP_WAIT(n)  asm volatile("cp.async.wait_group %0;" :: "n"(n) : "memory")

__device__ __forceinline__ void mma16(float* d, u32 a0, u32 a1, u32 a2, u32 a3,
                                      u32 b0, u32 b1) {
    asm volatile(
        "mma.sync.aligned.m16n8k16.row.col.f32.f16.f16.f32 "
        "{%0,%1,%2,%3}, {%4,%5,%6,%7}, {%8,%9}, {%0,%1,%2,%3};"
        : "+f"(d[0]), "+f"(d[1]), "+f"(d[2]), "+f"(d[3])
        : "r"(a0), "r"(a1), "r"(a2), "r"(a3), "r"(b0), "r"(b1));
}

// ---------------- prep / convert -------------------------------------------
__global__ void k_zero_out(float4* out) {
    out[blockIdx.x * blockDim.x + threadIdx.x] = make_float4(0.f, 0.f, 0.f, 0.f);
}
__global__ void k_x2h(const float2* __restrict__ x) {
    int i = blockIdx.x * blockDim.x + threadIdx.x;   // 1M threads, 2 el each
    float2 v = x[i];
    ((__half2*)d_xh)[i] = __floats2half2_rn(v.x, v.y);
}
__global__ __launch_bounds__(256) void k_prep(const int* __restrict__ ids32,
                                              const float* __restrict__ tw) {
    __shared__ int f;
    __shared__ int scnt[NEXP];
    __shared__ int sfill[NEXP];
    const int tid = threadIdx.x;
    if (tid < NEXP) scnt[tid] = 0;
    if (tid == 0) f = 0;
    __syncthreads();
    int local = 0;
    for (int i = tid; i < NA / 2; i += 256)
        if (ids32[2 * i + 1] != 0) local = 1;
    if (local) f = 1;
    __syncthreads();
    const int flag = f;   // 1 => int32 ids
    for (int i = tid; i < NA; i += 256) {
        int e = flag ? ids32[i] : ids32[2 * i];
        atomicAdd(&scnt[e], 1);
    }
    __syncthreads();
    if (tid == 0) {
        int off = 0;
        for (int e = 0; e < NEXP; e++) {
            d_off[e] = off; sfill[e] = off;
            d_count[e] = scnt[e];
            off += scnt[e];
        }
    }
    __syncthreads();
    for (int i = tid; i < NA; i += 256) {
        int e = flag ? ids32[i] : ids32[2 * i];
        int pos = atomicAdd(&sfill[e], 1);
        d_tok[pos] = i / TOPK;
        d_wts[pos] = tw[i];
    }
}

// ---------------- grouped fp16 GEMM ----------------------------------------
// BM=128, BK=32, 512 threads (16 warps). Warp tile 32x64: two 16-row stripes
// at rows (wid&3)*16 + mt*64 (SMSP-interleaved, mt<2), 64 cols at
// warpN=(wid>>2)*64.  A staged fp16, B staged fp32 + cvt at fragment load.
// MODE 0: BN=128 h-cols; B tile = 128 gate rows + 128 up rows (n0=bx*128).
//   N-groups 0,1 = gate cols, 2,3 = up cols; up accs -> smem; gate applies
//   silu(g)*u -> d_Hh.
// MODE 1: BN=256 (n0=bx*256), weighted atomic scatter into Out.
template<int KDIM, int MODE>
__global__ __launch_bounds__(512, 1) void k_gemm(const float* __restrict__ Bw,
                                                 float* __restrict__ Out) {
    constexpr int NIT = KDIM / 32;
    extern __shared__ char smem[];
    const int e = blockIdx.y;
    const int cnt = d_count[e];
    if (cnt == 0) return;
    const int row0e = d_off[e];
    const int n0 = blockIdx.x * (MODE == 0 ? 128 : 256);
    const long long bStride = (MODE == 0) ? (long long)GUN * HID
                                          : (long long)HID * FF;
    const __half* A = (MODE == 0) ? d_xh : d_Hh;

    const int tid = threadIdx.x;
    const int wid = tid >> 5, lane = tid & 31;
    const int r4 = lane >> 2, c4 = lane & 3;
    const int s16   = (wid & 3) * 16;       // SMSP-interleaved M base
    const int group = wid >> 2;             // 0..3 N-group
    const int warpN = group * 64;
    const u32 sb = smem_u32(smem);

    // B loader: 256 rows x 8 chunks = 2048 slots, 4/thread
    const int chunk = tid & 7, rb = tid >> 3;   // rb 0..63
    const float* bS[4];
    u32 bD[4];
#pragma unroll
    for (int p = 0; p < 4; p++) {
        int row = rb + 64 * p;
        long long gr = (MODE == 0)
            ? ((row < 128) ? (long long)(n0 + row)
                           : (long long)(FF + n0 + row - 128))
            : (long long)(n0 + row);
        bS[p] = Bw + (long long)e * bStride + gr * KDIM + chunk * 4;
        bD[p] = sb + BBASE + (u32)row * 160u + (u32)chunk * 16u;
    }

    for (int m0 = 0; m0 < cnt; m0 += 128) {
        // A loader: 128 rows x 4 chunks (64B rows) = 512 slots, 1/thread
        const int ar = tid >> 2, ach = tid & 3;
        int aval = (m0 + ar) < cnt;
        long long srow = 0;
        if (aval)
            srow = (MODE == 0) ? (long long)d_tok[row0e + m0 + ar]
                               : (long long)(row0e + m0 + ar);
        const __half* aS = A + srow * KDIM + ach * 8;
        const u32 aV = aval ? 16u : 0u;
        const u32 aD = sb + (u32)ar * 80u + (u32)ach * 16u;

        const int rem = cnt - m0;
        const int tv = rem - s16;
        const int mtMax = (tv <= 0) ? 0 : ((tv + 63) >> 6 > 2 ? 2 : (tv + 63) >> 6);

        float acc[2][8][4];
#pragma unroll
        for (int mt = 0; mt < 2; mt++)
#pragma unroll
            for (int nt = 0; nt < 8; nt++)
#pragma unroll
                for (int q = 0; q < 4; q++) acc[mt][nt][q] = 0.f;

#define ISSUE(s, k0) do {                                                  \
        u32 _ao = (u32)(s) * AST;                                          \
        u32 _bo = (u32)(s) * BST;                                          \
        CP16(aD + _ao, aS + (k0), aV);                                     \
        _Pragma("unroll")                                                  \
        for (int _p = 0; _p < 4; _p++)                                     \
            CP16(bD[_p] + _bo, bS[_p] + (k0), 16u);                        \
    } while (0)

        ISSUE(0, 0);  CP_COMMIT();
        ISSUE(1, 32); CP_COMMIT();
        ISSUE(2, 64); CP_COMMIT();

        for (int it = 0; it < NIT; it++) {
            const int buf = it & 3;
            CP_WAIT(2);
            __syncthreads();
            const int ns = it + 3;
            if (ns < NIT) ISSUE(ns & 3, ns * 32);
            CP_COMMIT();

            const __half* Ah = (const __half*)(smem + buf * AST);
            const float*  Bf = (const float*)(smem + BBASE + buf * BST);
#pragma unroll
            for (int ks = 0; ks < 2; ks++) {
                u32 b[8][2];
#pragma unroll
                for (int nt = 0; nt < 8; nt++) {
                    int cb = (warpN + nt * 8 + r4) * 40 + ks * 16 + 2 * c4;
                    b[nt][0] = pack2h(*(const float2*)&Bf[cb]);
                    b[nt][1] = pack2h(*(const float2*)&Bf[cb + 8]);
                }
#pragma unroll
                for (int mt = 0; mt < 2; mt++) {
                    if (mt < mtMax) {
                        int ab = (s16 + mt * 64 + r4) * 40 + ks * 16 + 2 * c4;
                        u32 a0 = *(const u32*)&Ah[ab];          // fp16x2 direct
                        u32 a1 = *(const u32*)&Ah[ab + 320];    // +8 rows
                        u32 a2 = *(const u32*)&Ah[ab + 8];      // +8 k
                        u32 a3 = *(const u32*)&Ah[ab + 328];
#pragma unroll
                        for (int nt = 0; nt < 8; nt++)
                            mma16(acc[mt][nt], a0, a1, a2, a3,
                                  b[nt][0], b[nt][1]);
                    }
                }
            }
        }
        CP_WAIT(0);

        if (MODE == 0) {
            // ---- fused SwiGLU epilogue: up groups -> smem, gate groups read
            float* xs = (float*)smem;
            __syncthreads();                    // pipeline smem now dead
            if (group >= 2) {
                const int xc = (group - 2) * 64;
#pragma unroll
                for (int mt = 0; mt < 2; mt++) {
                    int r = s16 + mt * 64 + r4;
#pragma unroll
                    for (int nt = 0; nt < 8; nt++) {
                        int col = xc + nt * 8 + c4 * 2;
                        *(float2*)&xs[r * XSTR + col] =
                            make_float2(acc[mt][nt][0], acc[mt][nt][1]);
                        *(float2*)&xs[(r + 8) * XSTR + col] =
                            make_float2(acc[mt][nt][2], acc[mt][nt][3]);
                    }
                }
            }
            __syncthreads();
            if (group < 2) {
                const int xc = group * 64;
#pragma unroll
                for (int mt = 0; mt < 2; mt++) {
                    int r = s16 + mt * 64 + r4;
                    int rloc = m0 + r;
#pragma unroll
                    for (int nt = 0; nt < 8; nt++) {
                        int col = xc + nt * 8 + c4 * 2;
                        if (rloc < cnt) {
                            float2 u = *(const float2*)&xs[r * XSTR + col];
                            float g0 = acc[mt][nt][0], g1 = acc[mt][nt][1];
                            float h0 = g0 / (1.f + __expf(-g0)) * u.x;
                            float h1 = g1 / (1.f + __expf(-g1)) * u.y;
                            *(__half2*)&d_Hh[(long long)(row0e + rloc) * FF
                                + n0 + col] = __floats2half2_rn(h0, h1);
                        }
                        if (rloc + 8 < cnt) {
                            float2 u = *(const float2*)&xs[(r + 8) * XSTR + col];
                            float g0 = acc[mt][nt][2], g1 = acc[mt][nt][3];
                            float h0 = g0 / (1.f + __expf(-g0)) * u.x;
                            float h1 = g1 / (1.f + __expf(-g1)) * u.y;
                            *(__half2*)&d_Hh[(long long)(row0e + rloc + 8) * FF
                                + n0 + col] = __floats2half2_rn(h0, h1);
                        }
                    }
                }
            }
        } else {
            // ---- weighted atomic scatter into Out ----
#pragma unroll
            for (int mt = 0; mt < 2; mt++) {
                int rloc = m0 + s16 + mt * 64 + r4;
                int v0 = rloc < cnt, v1 = (rloc + 8) < cnt;
                int t0 = 0, t1 = 0; float w0 = 0.f, w1 = 0.f;
                if (v0) { t0 = d_tok[row0e + rloc];     w0 = d_wts[row0e + rloc]; }
                if (v1) { t1 = d_tok[row0e + rloc + 8]; w1 = d_wts[row0e + rloc + 8]; }
#pragma unroll
                for (int nt = 0; nt < 8; nt++) {
                    int col = n0 + warpN + nt * 8 + c4 * 2;
                    if (v0) {
                        float* o = Out + (long long)t0 * HID + col;
                        atomicAdd(o,     w0 * acc[mt][nt][0]);
                        atomicAdd(o + 1, w0 * acc[mt][nt][1]);
                    }
                    if (v1) {
                        float* o = Out + (long long)t1 * HID + col;
                        atomicAdd(o,     w1 * acc[mt][nt][2]);
                        atomicAdd(o + 1, w1 * acc[mt][nt][3]);
                    }
                }
            }
        }
        __syncthreads();
#undef ISSUE
    }
}

// ---------------- launch ----------------------------------------------------
extern "C" void kernel_launch(void* const* d_in, const int* in_sizes, int n_in,
                              void* d_out, int out_size) {
    const float* x   = (const float*)d_in[0];
    const float* w1  = (const float*)d_in[1];
    const float* w2  = (const float*)d_in[2];
    const float* tw  = (const float*)d_in[3];
    const int*   ids = (const int*)d_in[4];
    float* out = (float*)d_out;

    cudaFuncSetAttribute(k_gemm<HID, 0>,
                         cudaFuncAttributeMaxDynamicSharedMemorySize, SMB);
    cudaFuncSetAttribute(k_gemm<FF, 1>,
                         cudaFuncAttributeMaxDynamicSharedMemorySize, SMB);

    k_zero_out<<<1024, 512>>>((float4*)out);
    k_x2h<<<2048, 512>>>((const float2*)x);
    k_prep<<<1, 256>>>(ids, tw);
    k_gemm<HID, 0><<<dim3(FF / 128, NEXP), 512, SMB>>>(w1, nullptr);
    k_gemm<FF, 1><<<dim3(HID / 256, NEXP), 512, SMB>>>(w2, out);
}

// round 13
// speedup vs baseline: 1.5828x; 1.3009x over previous
#include <cuda_runtime.h>
#include <cuda_fp16.h>

// ---------------------------------------------------------------------------
// Fused MoE via grouped fp16 mma.sync (m16n8k16) GEMMs, fp32 accumulate.
//   T=1024, H=2048, F=1408, E=32, K=6.
// zero_out -> prep -> x->fp16 -> GEMM1 (gate+up, fused SwiGLU -> Hb fp16)
//          -> GEMM2 (fused weighted atomic scatter -> out)
// R10 geometry (BM=256: weights staged exactly once; BN=64/128) + ldmatrix
// for A fragments (cuts consumer LDS ops 4x on the LSU-bound path).
// ---------------------------------------------------------------------------

#define T_TOK 1024
#define HID   2048
#define FF    1408
#define NEXP  32
#define TOPK  6
#define NA    (T_TOK * TOPK)    // 6144
#define GUN   (2 * FF)          // 2816

typedef unsigned int u32;

// smem: 4 stages: A 256 rows x 80B (fp16) = 20KB; B 128 rows x 160B (fp32)
// = 20KB.  A at [0,81920), B at [81920,163840).
#define AST   20480u
#define BBASE 81920u
#define BST   20480u
#define SMB   163840
#define XSTR  68                // swiglu exchange stride (floats)

// ---------------- device scratch -------------------------------------------
__device__ int    d_count[NEXP];
__device__ int    d_off[NEXP];
__device__ int    d_tok[NA];
__device__ float  d_wts[NA];
__device__ __half d_xh[(size_t)T_TOK * HID];   // x in fp16
__device__ __half d_Hh[(size_t)NA * FF];       // swiglu output in fp16

// ---------------- PTX helpers ----------------------------------------------
__device__ __forceinline__ u32 smem_u32(const void* p) {
    u32 a;
    asm("{ .reg .u64 t; cvta.to.shared.u64 t, %1; cvt.u32.u64 %0, t; }"
        : "=r"(a) : "l"(p));
    return a;
}
__device__ __forceinline__ u32 pack2h(float2 v) {   // {lo=v.x, hi=v.y} fp16x2
    u32 r;
    asm("cvt.rn.f16x2.f32 %0, %1, %2;" : "=r"(r) : "f"(v.y), "f"(v.x));
    return r;
}
#define CP16(dst, src, sz) \
    asm volatile("cp.async.cg.shared.global [%0], [%1], 16, %2;" \
                 :: "r"(dst), "l"(src), "r"(sz))
#define CP_COMMIT() asm volatile("cp.async.commit_group;" ::: "memory")
#define CP_WAIT(n)  asm volatile("cp.async.wait_group %0;" :: "n"(n) : "memory")
#define LDSM4(r0, r1, r2, r3, a) \
    asm volatile("ldmatrix.sync.aligned.m8n8.x4.shared.b16 {%0,%1,%2,%3}, [%4];" \
                 : "=r"(r0), "=r"(r1), "=r"(r2), "=r"(r3) : "r"(a))

__device__ __forceinline__ void mma16(float* d, u32 a0, u32 a1, u32 a2, u32 a3,
                                      u32 b0, u32 b1) {
    asm volatile(
        "mma.sync.aligned.m16n8k16.row.col.f32.f16.f16.f32 "
        "{%0,%1,%2,%3}, {%4,%5,%6,%7}, {%8,%9}, {%0,%1,%2,%3};"
        : "+f"(d[0]), "+f"(d[1]), "+f"(d[2]), "+f"(d[3])
        : "r"(a0), "r"(a1), "r"(a2), "r"(a3), "r"(b0), "r"(b1));
}

// ---------------- prep / convert -------------------------------------------
__global__ void k_zero_out(float4* out) {
    out[blockIdx.x * blockDim.x + threadIdx.x] = make_float4(0.f, 0.f, 0.f, 0.f);
}
__global__ void k_x2h(const float2* __restrict__ x) {
    int i = blockIdx.x * blockDim.x + threadIdx.x;   // 1M threads, 2 el each
    float2 v = x[i];
    ((__half2*)d_xh)[i] = __floats2half2_rn(v.x, v.y);
}
__global__ __launch_bounds__(256) void k_prep(const int* __restrict__ ids32,
                                              const float* __restrict__ tw) {
    __shared__ int f;
    __shared__ int scnt[NEXP];
    __shared__ int sfill[NEXP];
    const int tid = threadIdx.x;
    if (tid < NEXP) scnt[tid] = 0;
    if (tid == 0) f = 0;
    __syncthreads();
    int local = 0;
    for (int i = tid; i < NA / 2; i += 256)
        if (ids32[2 * i + 1] != 0) local = 1;
    if (local) f = 1;
    __syncthreads();
    const int flag = f;   // 1 => int32 ids
    for (int i = tid; i < NA; i += 256) {
        int e = flag ? ids32[i] : ids32[2 * i];
        atomicAdd(&scnt[e], 1);
    }
    __syncthreads();
    if (tid == 0) {
        int off = 0;
        for (int e = 0; e < NEXP; e++) {
            d_off[e] = off; sfill[e] = off;
            d_count[e] = scnt[e];
            off += scnt[e];
        }
    }
    __syncthreads();
    for (int i = tid; i < NA; i += 256) {
        int e = flag ? ids32[i] : ids32[2 * i];
        int pos = atomicAdd(&sfill[e], 1);
        d_tok[pos] = i / TOPK;
        d_wts[pos] = tw[i];
    }
}

// ---------------- grouped fp16 GEMM ----------------------------------------
// BM=256, BK=32, 512 threads (16 warps). Warp tile 64x32: four 16-row stripes
// at rows (wid&3)*16 + mt*64 (SMSP-interleaved), 32 cols at warpN=(wid>>2)*32.
// A staged fp16 + ldmatrix.x4 fragments; B staged fp32 + cvt at load.
// MODE 0: B tile = 64 gate rows + 64 up rows of same h-cols (n0=bx*64);
//   groups 0,1 gate / 2,3 up; up accs -> smem; gate applies silu*u -> d_Hh.
// MODE 1: BN=128 (n0=bx*128), weighted atomic scatter into Out.
template<int KDIM, int MODE>
__global__ __launch_bounds__(512, 1) void k_gemm(const float* __restrict__ Bw,
                                                 float* __restrict__ Out) {
    constexpr int NIT = KDIM / 32;
    extern __shared__ char smem[];
    const int e = blockIdx.y;
    const int cnt = d_count[e];
    if (cnt == 0) return;
    const int row0e = d_off[e];
    const int n0 = blockIdx.x * (MODE == 0 ? 64 : 128);
    const long long bStride = (MODE == 0) ? (long long)GUN * HID
                                          : (long long)HID * FF;
    const __half* A = (MODE == 0) ? d_xh : d_Hh;

    const int tid = threadIdx.x;
    const int wid = tid >> 5, lane = tid & 31;
    const int r4 = lane >> 2, c4 = lane & 3;
    const int s16   = (wid & 3) * 16;       // SMSP-interleaved M base
    const int group = wid >> 2;             // 0..3 N-group
    const int warpN = group * 32;
    const u32 sb = smem_u32(smem);

    // ldmatrix per-lane source offset within A tile:
    // quad 0: frag rows 0-7 k0-7 | quad 1: rows 8-15 k0-7
    // quad 2: rows 0-7 k8-15     | quad 3: rows 8-15 k8-15   (80B row stride)
    const int lq = lane & 7, quad = lane >> 3;
    const u32 ldsmOff = (u32)(((quad & 1) * 8 + lq) * 80 + (quad >> 1) * 16);

    // B loader: chunk = 16B slot (8 per 128B row), rb = 0..63, 2 rows/thread
    const int chunk = tid & 7, rb = tid >> 3;
    const float* bS[2];
    u32 bD[2];
#pragma unroll
    for (int p = 0; p < 2; p++) {
        int row = rb + 64 * p;
        long long gr = (MODE == 0)
            ? ((row < 64) ? (long long)(n0 + row) : (long long)(FF + n0 + row - 64))
            : (long long)(n0 + row);
        bS[p] = Bw + (long long)e * bStride + gr * KDIM + chunk * 4;
        bD[p] = sb + BBASE + (u32)row * 160u + (u32)chunk * 16u;
    }

    for (int m0 = 0; m0 < cnt; m0 += 256) {
        // A loader: 1024 16B-slots (4 per 64B fp16 row), 2 slots/thread
        const __half* aS[2];
        u32 aV[2], aD[2];
#pragma unroll
        for (int j = 0; j < 2; j++) {
            int slot = tid + 512 * j;
            int r = slot >> 2, ch = slot & 3;
            int valid = (m0 + r) < cnt;
            long long src = 0;
            if (valid)
                src = (MODE == 0) ? (long long)d_tok[row0e + m0 + r]
                                  : (long long)(row0e + m0 + r);
            aS[j] = A + src * KDIM + ch * 8;
            aV[j] = valid ? 16u : 0u;
            aD[j] = sb + (u32)r * 80u + (u32)ch * 16u;
        }
        const int rem = cnt - m0;
        const int tv = rem - s16;
        const int mtMax = (tv <= 0) ? 0 : ((tv + 63) >> 6 > 4 ? 4 : (tv + 63) >> 6);

        float acc[4][4][4];
#pragma unroll
        for (int mt = 0; mt < 4; mt++)
#pragma unroll
            for (int nt = 0; nt < 4; nt++)
#pragma unroll
                for (int q = 0; q < 4; q++) acc[mt][nt][q] = 0.f;

#define ISSUE(s, k0) do {                                                  \
        u32 _ao = (u32)(s) * AST;                                          \
        u32 _bo = (u32)(s) * BST;                                          \
        _Pragma("unroll")                                                  \
        for (int _j = 0; _j < 2; _j++)                                     \
            CP16(aD[_j] + _ao, aS[_j] + (k0), aV[_j]);                     \
        _Pragma("unroll")                                                  \
        for (int _p = 0; _p < 2; _p++)                                     \
            CP16(bD[_p] + _bo, bS[_p] + (k0), 16u);                        \
    } while (0)

        ISSUE(0, 0);  CP_COMMIT();
        ISSUE(1, 32); CP_COMMIT();
        ISSUE(2, 64); CP_COMMIT();

        for (int it = 0; it < NIT; it++) {
            const int buf = it & 3;
            CP_WAIT(2);
            __syncthreads();
            const int ns = it + 3;
            if (ns < NIT) ISSUE(ns & 3, ns * 32);
            CP_COMMIT();

            const u32 aBase = sb + buf * AST + ldsmOff;
            const float* Bf = (const float*)(smem + BBASE + buf * BST);
#pragma unroll
            for (int ks = 0; ks < 2; ks++) {
                u32 b[4][2];
#pragma unroll
                for (int nt = 0; nt < 4; nt++) {
                    int cb = (warpN + nt * 8 + r4) * 40 + ks * 16 + 2 * c4;
                    b[nt][0] = pack2h(*(const float2*)&Bf[cb]);
                    b[nt][1] = pack2h(*(const float2*)&Bf[cb + 8]);
                }
#pragma unroll
                for (int mt = 0; mt < 4; mt++) {
                    if (mt < mtMax) {
                        u32 a0, a1, a2, a3;
                        LDSM4(a0, a1, a2, a3,
                              aBase + (u32)(s16 + mt * 64) * 80u + (u32)ks * 32u);
#pragma unroll
                        for (int nt = 0; nt < 4; nt++)
                            mma16(acc[mt][nt], a0, a1, a2, a3,
                                  b[nt][0], b[nt][1]);
                    }
                }
            }
        }
        CP_WAIT(0);

        if (MODE == 0) {
            // ---- fused SwiGLU epilogue: up groups -> smem, gate groups read
            float* xs = (float*)smem;
            __syncthreads();                    // pipeline smem now dead
            if (group >= 2) {
                const int xc = (group - 2) * 32;
#pragma unroll
                for (int mt = 0; mt < 4; mt++) {
                    int r = s16 + mt * 64 + r4;
#pragma unroll
                    for (int nt = 0; nt < 4; nt++) {
                        int col = xc + nt * 8 + c4 * 2;
                        *(float2*)&xs[r * XSTR + col] =
                            make_float2(acc[mt][nt][0], acc[mt][nt][1]);
                        *(float2*)&xs[(r + 8) * XSTR + col] =
                            make_float2(acc[mt][nt][2], acc[mt][nt][3]);
                    }
                }
            }
            __syncthreads();
            if (group < 2) {
                const int xc = group * 32;
#pragma unroll
                for (int mt = 0; mt < 4; mt++) {
                    int r = s16 + mt * 64 + r4;
                    int rloc = m0 + r;
#pragma unroll
                    for (int nt = 0; nt < 4; nt++) {
                        int col = xc + nt * 8 + c4 * 2;
                        if (rloc < cnt) {
                            float2 u = *(const float2*)&xs[r * XSTR + col];
                            float g0 = acc[mt][nt][0], g1 = acc[mt][nt][1];
                            float h0 = g0 / (1.f + __expf(-g0)) * u.x;
                            float h1 = g1 / (1.f + __expf(-g1)) * u.y;
                            *(__half2*)&d_Hh[(long long)(row0e + rloc) * FF
                                + n0 + col] = __floats2half2_rn(h0, h1);
                        }
                        if (rloc + 8 < cnt) {
                            float2 u = *(const float2*)&xs[(r + 8) * XSTR + col];
                            float g0 = acc[mt][nt][2], g1 = acc[mt][nt][3];
                            float h0 = g0 / (1.f + __expf(-g0)) * u.x;
                            float h1 = g1 / (1.f + __expf(-g1)) * u.y;
                            *(__half2*)&d_Hh[(long long)(row0e + rloc + 8) * FF
                                + n0 + col] = __floats2half2_rn(h0, h1);
                        }
                    }
                }
            }
        } else {
            // ---- weighted atomic scatter into Out ----
#pragma unroll
            for (int mt = 0; mt < 4; mt++) {
                int rloc = m0 + s16 + mt * 64 + r4;
                int v0 = rloc < cnt, v1 = (rloc + 8) < cnt;
                int t0 = 0, t1 = 0; float w0 = 0.f, w1 = 0.f;
                if (v0) { t0 = d_tok[row0e + rloc];     w0 = d_wts[row0e + rloc]; }
                if (v1) { t1 = d_tok[row0e + rloc + 8]; w1 = d_wts[row0e + rloc + 8]; }
#pragma unroll
                for (int nt = 0; nt < 4; nt++) {
                    int col = n0 + warpN + nt * 8 + c4 * 2;
                    if (v0) {
                        float* o = Out + (long long)t0 * HID + col;
                        atomicAdd(o,     w0 * acc[mt][nt][0]);
                        atomicAdd(o + 1, w0 * acc[mt][nt][1]);
                    }
                    if (v1) {
                        float* o = Out + (long long)t1 * HID + col;
                        atomicAdd(o,     w1 * acc[mt][nt][2]);
                        atomicAdd(o + 1, w1 * acc[mt][nt][3]);
                    }
                }
            }
        }
        __syncthreads();
#undef ISSUE
    }
}

// ---------------- launch ----------------------------------------------------
extern "C" void kernel_launch(void* const* d_in, const int* in_sizes, int n_in,
                              void* d_out, int out_size) {
    const float* x   = (const float*)d_in[0];
    const float* w1  = (const float*)d_in[1];
    const float* w2  = (const float*)d_in[2];
    const float* tw  = (const float*)d_in[3];
    const int*   ids = (const int*)d_in[4];
    float* out = (float*)d_out;

    cudaFuncSetAttribute(k_gemm<HID, 0>,
                         cudaFuncAttributeMaxDynamicSharedMemorySize, SMB);
    cudaFuncSetAttribute(k_gemm<FF, 1>,
                         cudaFuncAttributeMaxDynamicSharedMemorySize, SMB);

    k_zero_out<<<1024, 512>>>((float4*)out);
    k_x2h<<<2048, 512>>>((const float2*)x);
    k_prep<<<1, 256>>>(ids, tw);
    k_gemm<HID, 0><<<dim3(FF / 64, NEXP), 512, SMB>>>(w1, nullptr);
    k_gemm<FF, 1><<<dim3(HID / 128, NEXP), 512, SMB>>>(w2, out);
}